// round 14
// baseline (speedup 1.0000x reference)
#include <cuda_runtime.h>
#include <cuda_bf16.h>
#include <math.h>

#define Bn    8
#define Ln    2048
#define KSEL  64
#define EXCL  3
#define NAA   20
#define EMB   16
#define MD    7
#define D2CUT 144.0f      // r >= 12 -> smoothstep == 0 -> zero energy
#define BCAP  256         // bucket capacity before radix fallback
#define CANDN 1024        // flat candidate buffer (E[max] ~620, 19 sigma)
#define BINSCALE (256.0f / 144.0f)

// Scratch (device globals: no allocation allowed)
__device__ float g_rowsum[Bn * Ln];
__device__ float g_tab[NAA * NAA * MD];       // softplus(MLP(aa_i,aa_j))
__device__ unsigned g_done[Bn];               // per-batch completion tickets

// ---------------------------------------------------------------------------
// Kernel 0: exact fp32 MLP over 400 AA pairs -> 400x7 table.
// 2 pairs/block (ILP-2), 1024 threads, 8-way K-split (short serial chains).
// ---------------------------------------------------------------------------
__global__ void __launch_bounds__(1024) table_kernel(
    const float* __restrict__ emb,
    const float* __restrict__ W1, const float* __restrict__ b1,
    const float* __restrict__ W2, const float* __restrict__ b2,
    const float* __restrict__ W3, const float* __restrict__ b3)
{
    __shared__ float x[2][48];
    __shared__ float h1[2][128];
    __shared__ float h2[2][128];
    __shared__ float part[2][8][128];

    const int p0 = blockIdx.x * 2;
    const int tid = threadIdx.x;
    const int n = tid & 127;
    const int q8 = tid >> 7;            // 0..7

    if (tid < 2 * EMB) {
        int pr = tid >> 4, c = tid & 15;
        int p = p0 + pr;
        float ei = emb[(p / NAA) * EMB + c];
        float ej = emb[(p % NAA) * EMB + c];
        x[pr][c] = ei; x[pr][EMB + c] = ej; x[pr][2 * EMB + c] = ei * ej;
    }
    __syncthreads();

    {   // Layer 1: K=48, 8 x 6
        float a0 = 0.f, a1 = 0.f;
        const int k0 = q8 * 6;
        #pragma unroll
        for (int k = 0; k < 6; k++) {
            float w = W1[(k0 + k) * 128 + n];
            a0 = fmaf(x[0][k0 + k], w, a0);
            a1 = fmaf(x[1][k0 + k], w, a1);
        }
        part[0][q8][n] = a0; part[1][q8][n] = a1;
    }
    __syncthreads();
    if (q8 < 2) {
        float s = b1[n];
        #pragma unroll
        for (int q = 0; q < 8; q++) s += part[q8][q][n];
        h1[q8][n] = fmaxf(s, 0.f);
    }
    __syncthreads();

    {   // Layer 2: K=128, 8 x 16
        float a0 = 0.f, a1 = 0.f;
        const int k0 = q8 * 16;
        #pragma unroll
        for (int k = 0; k < 16; k++) {
            float w = W2[(k0 + k) * 128 + n];
            a0 = fmaf(h1[0][k0 + k], w, a0);
            a1 = fmaf(h1[1][k0 + k], w, a1);
        }
        part[0][q8][n] = a0; part[1][q8][n] = a1;
    }
    __syncthreads();
    if (q8 < 2) {
        float s = b2[n];
        #pragma unroll
        for (int q = 0; q < 8; q++) s += part[q8][q][n];
        h2[q8][n] = fmaxf(s, 0.f);
    }
    __syncthreads();

    if (tid < 2 * MD * 8) {   // Layer 3: K=128, 8 x 16, 7 outs x 2 pairs
        int pr = tid / 56, rem = tid % 56;
        int m = rem % MD, qq = rem / MD;
        float a = 0.f;
        const int k0 = qq * 16;
        #pragma unroll
        for (int k = 0; k < 16; k++)
            a = fmaf(h2[pr][k0 + k], W3[(k0 + k) * MD + m], a);
        part[pr][qq][m] = a;
    }
    __syncthreads();
    if (tid < 2 * MD) {
        int pr = tid / MD, m = tid % MD;
        float a = b3[m];
        #pragma unroll
        for (int q = 0; q < 8; q++) a += part[pr][q][m];
        float sp = fmaxf(a, 0.f) + log1pf(expf(-fabsf(a)));  // jax softplus
        g_tab[(p0 + pr) * MD + m] = sp;
    }
}

// ---------------------------------------------------------------------------
// Per-pair energy: table lookup + anchored RBF product chain + smoothstep.
// ---------------------------------------------------------------------------
__device__ __forceinline__ float pair_energy(float d2, int jj,
                                             const int* __restrict__ seqb,
                                             int aa_base)
{
    float r = sqrtf(d2);
    int aj = __ldg(seqb + jj);
    const float* tp = g_tab + (aa_base + aj) * MD;
    const float C2  = 0.13533528323661270f;      // e^-2
    const float C6  = 2.4787521766663585e-3f;    // e^-6
    const float C10 = 4.5399929762484854e-5f;    // e^-10
    float t  = r - 8.f;
    float p3 = __expf(-2.f * t * t);
    float G  = __expf( 4.f * t);
    float Gi = __expf(-4.f * t);
    float p4 = p3 * G  * C2;
    float p5 = p4 * G  * C6;
    float p6 = p5 * G  * C10;
    float p2 = p3 * Gi * C2;
    float p1 = p2 * Gi * C6;
    float p0 = p1 * Gi * C10;
    float att = tp[0] * p0 + tp[1] * p1 + tp[2] * p2 + tp[3] * p3
              + tp[4] * p4 + tp[5] * p5 + tp[6] * p6;
    float tt = fminf(fmaxf((r - 10.f) * 0.5f, 0.f), 1.f);
    float sw = 1.f - tt * tt * (3.f - 2.f * tt);
    return -att * sw;
}

// ---------------------------------------------------------------------------
// Kernel 1: one row per CTA, __launch_bounds__(256, 8). R7 scan + flat select
// + fused last-CTA-per-batch final reduction (decoupled, deterministic tree).
// key = (bits(d2) << 11) | j  (43 bits, unique). Exact fallbacks retained.
// ---------------------------------------------------------------------------
__global__ void __launch_bounds__(256, 8) topk_energy_kernel(
    const float* __restrict__ R, const int* __restrict__ seq,
    float* __restrict__ out)
{
    __shared__ unsigned long long seg[8 * 256];    // 16 KB
    __shared__ unsigned long long cand[CANDN];     // 8 KB
    __shared__ unsigned long long buf[BCAP];       // 2 KB
    __shared__ int hist[256];
    __shared__ int s_cnt[8];
    __shared__ int wtot[8];
    __shared__ float wsum[8];
    __shared__ int s_B, s_targ, s_bcnt, s_last;
    __shared__ unsigned long long s_T;
    __shared__ unsigned long long s_pref;

    const int tid = threadIdx.x;
    const int w = tid >> 5, lane = tid & 31;
    const unsigned lanelt = (1u << lane) - 1u;
    const int row = blockIdx.x;
    const int b = row >> 11;
    const int i = row & (Ln - 1);
    const float* __restrict__ Rb = R + (size_t)b * Ln * 3;
    const int* __restrict__ seqb = seq + b * Ln;

    const float xi = Rb[3 * i], yi = Rb[3 * i + 1], zi = Rb[3 * i + 2];

    if (tid == 0) { s_bcnt = 0; s_T = ~0ull; }

    // --- Scan: warp w owns j in [256w, 256w+256), ballot compaction ---
    int cnt = 0;
    #pragma unroll
    for (int it = 0; it < 8; it++) {
        const int j = (w << 8) + (it << 5) + lane;
        float dx = xi - Rb[3 * j];
        float dy = yi - Rb[3 * j + 1];
        float dz = zi - Rb[3 * j + 2];
        float d2 = fmaf(dx, dx, fmaf(dy, dy, fmaf(dz, dz, 1e-12f)));
        bool p = (d2 < D2CUT) && ((unsigned)(j - i + EXCL) > 2u * EXCL);
        unsigned m = __ballot_sync(0xffffffffu, p);
        if (p) {
            seg[(w << 8) + cnt + __popc(m & lanelt)] =
                (((unsigned long long)__float_as_uint(d2)) << 11) | (unsigned)j;
        }
        cnt += __popc(m);
    }
    if (lane == 0) s_cnt[w] = cnt;
    __syncthreads();

    int ctot = 0;
    #pragma unroll
    for (int s = 0; s < 8; s++) ctot += s_cnt[s];

    const int aa_base = __ldg(seqb + i) * NAA;
    float local = 0.f;

    if (ctot <= CANDN) {
        // ===================== FLAT FAST PATH =====================
        {
            int off = 0;
            #pragma unroll
            for (int s = 0; s < 8; s++) {
                int cs = s_cnt[s];
                if (tid < cs) cand[off + tid] = seg[(s << 8) + tid];
                off += cs;
            }
        }
        hist[tid] = 0;
        __syncthreads();

        if (ctot > KSEL) {
            // --- 1-round 256-bin linear-d2 histogram ---
            for (int g = tid; g < ctot; g += 256) {
                float d2 = __uint_as_float((unsigned)(cand[g] >> 11));
                atomicAdd(&hist[min((int)(d2 * BINSCALE), 255)], 1);
            }
            __syncthreads();

            // --- Block inclusive scan over bins, find crossing bin ---
            int v = hist[tid];
            int incl = v;
            #pragma unroll
            for (int o = 1; o < 32; o <<= 1) {
                int t = __shfl_up_sync(0xffffffffu, incl, o);
                if (lane >= o) incl += t;
            }
            if (lane == 31) wtot[w] = incl;
            __syncthreads();
            if (tid == 0) {
                int r = 0;
                #pragma unroll
                for (int q = 0; q < 8; q++) { int t = wtot[q]; wtot[q] = r; r += t; }
            }
            __syncthreads();
            incl += wtot[w];
            int excl = incl - v;
            if (excl < KSEL && KSEL <= incl) { s_B = tid; s_targ = KSEL - excl; }
            __syncthreads();
            const int B = s_B;

            // --- Gather bucket + fused below-bucket energy ---
            for (int g = tid; g < ctot; g += 256) {
                unsigned long long key = cand[g];
                float d2 = __uint_as_float((unsigned)(key >> 11));
                int bin = min((int)(d2 * BINSCALE), 255);
                if (bin < B) {
                    local += pair_energy(d2, (int)(key & 2047ull), seqb, aa_base);
                } else if (bin == B) {
                    int pos = atomicAdd(&s_bcnt, 1);
                    if (pos < BCAP) buf[pos] = key;
                }
            }
            __syncthreads();
            const int bc = s_bcnt;

            if (bc <= BCAP) {
                // --- Exact threshold by warp-0 rank count (unique keys) ---
                if (tid < 32) {
                    const int tg = s_targ;
                    for (int c = lane; c < bc; c += 32) {
                        unsigned long long key = buf[c];
                        int rank = 0;
                        for (int t = 0; t < bc; t++) rank += (buf[t] < key);
                        if (rank == tg - 1) s_T = key;
                    }
                }
                __syncthreads();
                const unsigned long long T = s_T;
                for (int g = tid; g < bc; g += 256) {
                    unsigned long long key = buf[g];
                    if (key <= T) {
                        float d2 = __uint_as_float((unsigned)(key >> 11));
                        local += pair_energy(d2, (int)(key & 2047ull), seqb, aa_base);
                    }
                }
            } else {
                // --- Bucket overflow (never expected): exact flat radix ---
                local = 0.f;
                if (tid == 0) { s_pref = 0ull; s_targ = KSEL; }
                __syncthreads();
                for (int pass = 0; pass < 6; pass++) {
                    const int shift = 40 - 8 * pass;
                    hist[tid] = 0;
                    __syncthreads();
                    const unsigned long long hp = s_pref >> (shift + 8);
                    for (int g = tid; g < ctot; g += 256) {
                        unsigned long long key = cand[g];
                        if ((key >> (shift + 8)) == hp)
                            atomicAdd(&hist[(int)((key >> shift) & 255)], 1);
                    }
                    __syncthreads();
                    if (tid < 32) {
                        const int base = tid * 8;
                        int c8[8]; int ssum = 0;
                        #pragma unroll
                        for (int t = 0; t < 8; t++) { c8[t] = hist[base + t]; ssum += c8[t]; }
                        int incl2 = ssum;
                        #pragma unroll
                        for (int o = 1; o < 32; o <<= 1) {
                            int t = __shfl_up_sync(0xffffffffu, incl2, o);
                            if (tid >= o) incl2 += t;
                        }
                        int excl2 = incl2 - ssum;
                        const int tgt = s_targ;
                        const unsigned long long pref = s_pref;
                        __syncwarp();
                        int run = excl2;
                        #pragma unroll
                        for (int t = 0; t < 8; t++) {
                            if (run < tgt && tgt <= run + c8[t]) {
                                s_pref = pref | ((unsigned long long)(base + t) << shift);
                                s_targ = tgt - run;
                            }
                            run += c8[t];
                        }
                    }
                    __syncthreads();
                }
                const unsigned long long T = s_pref;
                for (int g = tid; g < ctot; g += 256) {
                    unsigned long long key = cand[g];
                    if (key <= T) {
                        float d2 = __uint_as_float((unsigned)(key >> 11));
                        local += pair_energy(d2, (int)(key & 2047ull), seqb, aa_base);
                    }
                }
            }
        } else {
            // ctot <= KSEL: every candidate contributes
            for (int g = tid; g < ctot; g += 256) {
                unsigned long long key = cand[g];
                float d2 = __uint_as_float((unsigned)(key >> 11));
                local += pair_energy(d2, (int)(key & 2047ull), seqb, aa_base);
            }
        }
    } else {
        // ===== SLOW PATH (ctot > CANDN, never expected): segment-major =====
        hist[tid] = 0;
        __syncthreads();
        #pragma unroll 1
        for (int s = 0; s < 8; s++) {
            const int cs = s_cnt[s];
            for (int c = tid; c < cs; c += 256) {
                float d2 = __uint_as_float((unsigned)(seg[(s << 8) + c] >> 11));
                atomicAdd(&hist[min((int)(d2 * BINSCALE), 255)], 1);
            }
        }
        __syncthreads();

        int v = hist[tid];
        int incl = v;
        #pragma unroll
        for (int o = 1; o < 32; o <<= 1) {
            int t = __shfl_up_sync(0xffffffffu, incl, o);
            if (lane >= o) incl += t;
        }
        if (lane == 31) wtot[w] = incl;
        __syncthreads();
        if (tid == 0) {
            int r = 0;
            #pragma unroll
            for (int q = 0; q < 8; q++) { int t = wtot[q]; wtot[q] = r; r += t; }
        }
        __syncthreads();
        incl += wtot[w];
        int excl = incl - v;
        if (excl < KSEL && KSEL <= incl) { s_B = tid; s_targ = KSEL - excl; }
        __syncthreads();
        const int B = s_B;

        #pragma unroll 1
        for (int s = 0; s < 8; s++) {
            const int cs = s_cnt[s];
            for (int c = tid; c < cs; c += 256) {
                unsigned long long key = seg[(s << 8) + c];
                float d2 = __uint_as_float((unsigned)(key >> 11));
                int bin = min((int)(d2 * BINSCALE), 255);
                if (bin == B) {
                    int pos = atomicAdd(&s_bcnt, 1);
                    if (pos < BCAP) buf[pos] = key;
                }
            }
        }
        __syncthreads();
        const int bc = s_bcnt;

        if (bc <= BCAP) {
            if (tid < 32) {
                const int tg = s_targ;
                for (int c = lane; c < bc; c += 32) {
                    unsigned long long key = buf[c];
                    int rank = 0;
                    for (int t = 0; t < bc; t++) rank += (buf[t] < key);
                    if (rank == tg - 1) s_T = key;
                }
            }
            __syncthreads();
        } else {
            if (tid == 0) { s_pref = 0ull; s_targ = KSEL; }
            __syncthreads();
            for (int pass = 0; pass < 6; pass++) {
                const int shift = 40 - 8 * pass;
                hist[tid] = 0;
                __syncthreads();
                const unsigned long long hp = s_pref >> (shift + 8);
                for (int s = 0; s < 8; s++) {
                    const int cs = s_cnt[s];
                    for (int c = tid; c < cs; c += 256) {
                        unsigned long long key = seg[(s << 8) + c];
                        if ((key >> (shift + 8)) == hp)
                            atomicAdd(&hist[(int)((key >> shift) & 255)], 1);
                    }
                }
                __syncthreads();
                if (tid < 32) {
                    const int base = tid * 8;
                    int c8[8]; int ssum = 0;
                    #pragma unroll
                    for (int t = 0; t < 8; t++) { c8[t] = hist[base + t]; ssum += c8[t]; }
                    int incl2 = ssum;
                    #pragma unroll
                    for (int o = 1; o < 32; o <<= 1) {
                        int t = __shfl_up_sync(0xffffffffu, incl2, o);
                        if (tid >= o) incl2 += t;
                    }
                    int excl2 = incl2 - ssum;
                    const int tgt = s_targ;
                    const unsigned long long pref = s_pref;
                    __syncwarp();
                    int run = excl2;
                    #pragma unroll
                    for (int t = 0; t < 8; t++) {
                        if (run < tgt && tgt <= run + c8[t]) {
                            s_pref = pref | ((unsigned long long)(base + t) << shift);
                            s_targ = tgt - run;
                        }
                        run += c8[t];
                    }
                }
                __syncthreads();
            }
            if (tid == 0) s_T = s_pref;
            __syncthreads();
        }

        const unsigned long long T = s_T;
        #pragma unroll 1
        for (int s = 0; s < 8; s++) {
            const int cs = s_cnt[s];
            for (int c = tid; c < cs; c += 256) {
                unsigned long long key = seg[(s << 8) + c];
                if (key <= T) {
                    float d2 = __uint_as_float((unsigned)(key >> 11));
                    local += pair_energy(d2, (int)(key & 2047ull), seqb, aa_base);
                }
            }
        }
    }

    // --- Deterministic block reduction + decoupled last-CTA batch reduce ---
    #pragma unroll
    for (int o = 16; o > 0; o >>= 1)
        local += __shfl_down_sync(0xffffffffu, local, o);
    if (lane == 0) wsum[w] = local;
    __syncthreads();
    if (tid == 0) {
        float s = 0.f;
        #pragma unroll
        for (int q = 0; q < 8; q++) s += wsum[q];
        g_rowsum[row] = s;
        __threadfence();
        unsigned t = atomicAdd(&g_done[b], 1u);
        s_last = (t == (unsigned)(Ln - 1)) ? 1 : 0;
        if (s_last) g_done[b] = 0;            // reset for next graph replay
    }
    __syncthreads();

    if (s_last) {
        // This CTA is the last of its batch: all 2048 rowsums are visible.
        float* red = (float*)hist;            // reuse smem (hist dead here)
        float v = 0.f;
        #pragma unroll
        for (int k = 0; k < Ln / 256; k++) {
            float val;
            asm volatile("ld.global.cg.f32 %0, [%1];"
                         : "=f"(val)
                         : "l"(g_rowsum + b * Ln + k * 256 + tid));
            v += val;
        }
        red[tid] = v;
        __syncthreads();
        #pragma unroll
        for (int o = 128; o > 0; o >>= 1) {
            if (tid < o) red[tid] += red[tid + o];
            __syncthreads();
        }
        if (tid == 0) out[b] = red[0];
    }
}

// ---------------------------------------------------------------------------
extern "C" void kernel_launch(void* const* d_in, const int* in_sizes, int n_in,
                              void* d_out, int out_size)
{
    const float* R       = (const float*)d_in[0];
    const int*   seq     = (const int*)  d_in[1];
    const float* emb     = (const float*)d_in[2];
    const float* W1      = (const float*)d_in[3];
    const float* b1      = (const float*)d_in[4];
    const float* W2      = (const float*)d_in[5];
    const float* b2      = (const float*)d_in[6];
    const float* W3      = (const float*)d_in[7];
    const float* b3      = (const float*)d_in[8];
    float* out = (float*)d_out;

    table_kernel<<<NAA * NAA / 2, 1024>>>(emb, W1, b1, W2, b2, W3, b3);
    topk_energy_kernel<<<Bn * Ln, 256>>>(R, seq, out);
}

// round 15
// speedup vs baseline: 1.0021x; 1.0021x over previous
#include <cuda_runtime.h>
#include <cuda_bf16.h>
#include <math.h>

#define Bn    8
#define Ln    2048
#define KSEL  64
#define EXCL  3
#define NAA   20
#define EMB   16
#define MD    7
#define D2CUT 144.0f      // r >= 12 -> smoothstep == 0 -> zero energy
#define BCAP  256         // bucket capacity before radix fallback
#define CANDN 1024        // flat candidate buffer (E[max] ~620, 19 sigma)
#define BINSCALE (256.0f / 144.0f)

// Scratch (device globals: no allocation allowed)
__device__ float4 g_R4[Bn * Ln];              // padded coords (x,y,z,0)
__device__ float g_rowsum[Bn * Ln];
__device__ float g_tab[NAA * NAA * MD];       // softplus(MLP(aa_i,aa_j))

// ---------------------------------------------------------------------------
// Kernel T: pad R (stride 3) -> float4 (stride 4): 1 LDG.128 per j in scans
// ---------------------------------------------------------------------------
__global__ void __launch_bounds__(256) pad_kernel(const float* __restrict__ R)
{
    int p = blockIdx.x * 256 + threadIdx.x;
    float x = R[3 * p + 0];
    float y = R[3 * p + 1];
    float z = R[3 * p + 2];
    g_R4[p] = make_float4(x, y, z, 0.f);
}

// ---------------------------------------------------------------------------
// Kernel 0: exact fp32 MLP over 400 AA pairs -> 400x7 table.
// 2 pairs/block (ILP-2), 512 threads, 4-way K-split (short serial chains).
// ---------------------------------------------------------------------------
__global__ void __launch_bounds__(512) table_kernel(
    const float* __restrict__ emb,
    const float* __restrict__ W1, const float* __restrict__ b1,
    const float* __restrict__ W2, const float* __restrict__ b2,
    const float* __restrict__ W3, const float* __restrict__ b3)
{
    __shared__ float x[2][48];
    __shared__ float h1[2][128];
    __shared__ float h2[2][128];
    __shared__ float part[2][4][128];

    const int p0 = blockIdx.x * 2;
    const int tid = threadIdx.x;
    const int n = tid & 127;
    const int q4 = tid >> 7;            // 0..3

    if (tid < 2 * EMB) {
        int pr = tid >> 4, c = tid & 15;
        int p = p0 + pr;
        float ei = emb[(p / NAA) * EMB + c];
        float ej = emb[(p % NAA) * EMB + c];
        x[pr][c] = ei; x[pr][EMB + c] = ej; x[pr][2 * EMB + c] = ei * ej;
    }
    __syncthreads();

    {   // Layer 1: K=48, 4 x 12
        float a0 = 0.f, a1 = 0.f;
        const int k0 = q4 * 12;
        #pragma unroll
        for (int k = 0; k < 12; k++) {
            float w = W1[(k0 + k) * 128 + n];
            a0 = fmaf(x[0][k0 + k], w, a0);
            a1 = fmaf(x[1][k0 + k], w, a1);
        }
        part[0][q4][n] = a0; part[1][q4][n] = a1;
    }
    __syncthreads();
    if (q4 < 2)
        h1[q4][n] = fmaxf(b1[n] + part[q4][0][n] + part[q4][1][n]
                                + part[q4][2][n] + part[q4][3][n], 0.f);
    __syncthreads();

    {   // Layer 2: K=128, 4 x 32
        float a0 = 0.f, a1 = 0.f;
        const int k0 = q4 * 32;
        #pragma unroll
        for (int k = 0; k < 32; k++) {
            float w = W2[(k0 + k) * 128 + n];
            a0 = fmaf(h1[0][k0 + k], w, a0);
            a1 = fmaf(h1[1][k0 + k], w, a1);
        }
        part[0][q4][n] = a0; part[1][q4][n] = a1;
    }
    __syncthreads();
    if (q4 < 2)
        h2[q4][n] = fmaxf(b2[n] + part[q4][0][n] + part[q4][1][n]
                                + part[q4][2][n] + part[q4][3][n], 0.f);
    __syncthreads();

    if (tid < 2 * MD * 4) {   // Layer 3: K=128, 4 x 32, 7 outs x 2 pairs
        int pr = tid / 28, rem = tid % 28;
        int m = rem % MD, qq = rem / MD;
        float a = 0.f;
        const int k0 = qq * 32;
        #pragma unroll
        for (int k = 0; k < 32; k++)
            a = fmaf(h2[pr][k0 + k], W3[(k0 + k) * MD + m], a);
        part[pr][qq][m] = a;
    }
    __syncthreads();
    if (tid < 2 * MD) {
        int pr = tid / MD, m = tid % MD;
        float a = b3[m] + part[pr][0][m] + part[pr][1][m]
                        + part[pr][2][m] + part[pr][3][m];
        float sp = fmaxf(a, 0.f) + log1pf(expf(-fabsf(a)));  // jax softplus
        g_tab[(p0 + pr) * MD + m] = sp;
    }
}

// ---------------------------------------------------------------------------
// Per-pair energy: table lookup + anchored RBF product chain + smoothstep.
// ---------------------------------------------------------------------------
__device__ __forceinline__ float pair_energy(float d2, int jj,
                                             const int* __restrict__ seqb,
                                             int aa_base)
{
    float r = sqrtf(d2);
    int aj = __ldg(seqb + jj);
    const float* tp = g_tab + (aa_base + aj) * MD;
    const float C2  = 0.13533528323661270f;      // e^-2
    const float C6  = 2.4787521766663585e-3f;    // e^-6
    const float C10 = 4.5399929762484854e-5f;    // e^-10
    float t  = r - 8.f;
    float p3 = __expf(-2.f * t * t);
    float G  = __expf( 4.f * t);
    float Gi = __expf(-4.f * t);
    float p4 = p3 * G  * C2;
    float p5 = p4 * G  * C6;
    float p6 = p5 * G  * C10;
    float p2 = p3 * Gi * C2;
    float p1 = p2 * Gi * C6;
    float p0 = p1 * Gi * C10;
    float att = tp[0] * p0 + tp[1] * p1 + tp[2] * p2 + tp[3] * p3
              + tp[4] * p4 + tp[5] * p5 + tp[6] * p6;
    float tt = fminf(fmaxf((r - 10.f) * 0.5f, 0.f), 1.f);
    float sw = 1.f - tt * tt * (3.f - 2.f * tt);
    return -att * sw;
}

// ---------------------------------------------------------------------------
// Kernel 1: one row per CTA, __launch_bounds__(256, 8). float4 scan loads
// (occupancy now pinned — clean experiment) + flat-compacted select.
// key = (bits(d2) << 11) | j  (43 bits, unique). Exact fallbacks retained.
// ---------------------------------------------------------------------------
__global__ void __launch_bounds__(256, 8) topk_energy_kernel(const int* __restrict__ seq)
{
    __shared__ unsigned long long seg[8 * 256];    // 16 KB
    __shared__ unsigned long long cand[CANDN];     // 8 KB
    __shared__ unsigned long long buf[BCAP];       // 2 KB
    __shared__ int hist[256];
    __shared__ int s_cnt[8];
    __shared__ int wtot[8];
    __shared__ float wsum[8];
    __shared__ int s_B, s_targ, s_bcnt;
    __shared__ unsigned long long s_T;
    __shared__ unsigned long long s_pref;

    const int tid = threadIdx.x;
    const int w = tid >> 5, lane = tid & 31;
    const unsigned lanelt = (1u << lane) - 1u;
    const int row = blockIdx.x;
    const int b = row >> 11;
    const int i = row & (Ln - 1);
    const float4* __restrict__ R4b = g_R4 + b * Ln;
    const int* __restrict__ seqb = seq + b * Ln;

    const float4 ri = __ldg(R4b + i);
    const float xi = ri.x, yi = ri.y, zi = ri.z;

    if (tid == 0) { s_bcnt = 0; s_T = ~0ull; }

    // --- Scan: warp w owns j in [256w, 256w+256); 1 LDG.128 per j ---
    int cnt = 0;
    #pragma unroll
    for (int it = 0; it < 8; it++) {
        const int j = (w << 8) + (it << 5) + lane;
        float4 rj = __ldg(R4b + j);
        float dx = xi - rj.x;
        float dy = yi - rj.y;
        float dz = zi - rj.z;
        float d2 = fmaf(dx, dx, fmaf(dy, dy, fmaf(dz, dz, 1e-12f)));
        bool p = (d2 < D2CUT) && ((unsigned)(j - i + EXCL) > 2u * EXCL);
        unsigned m = __ballot_sync(0xffffffffu, p);
        if (p) {
            seg[(w << 8) + cnt + __popc(m & lanelt)] =
                (((unsigned long long)__float_as_uint(d2)) << 11) | (unsigned)j;
        }
        cnt += __popc(m);
    }
    if (lane == 0) s_cnt[w] = cnt;
    __syncthreads();

    int ctot = 0;
    #pragma unroll
    for (int s = 0; s < 8; s++) ctot += s_cnt[s];

    const int aa_base = __ldg(seqb + i) * NAA;
    float local = 0.f;

    if (ctot <= CANDN) {
        // ===================== FLAT FAST PATH =====================
        {
            int off = 0;
            #pragma unroll
            for (int s = 0; s < 8; s++) {
                int cs = s_cnt[s];
                if (tid < cs) cand[off + tid] = seg[(s << 8) + tid];
                off += cs;
            }
        }
        hist[tid] = 0;
        __syncthreads();

        if (ctot > KSEL) {
            // --- 1-round 256-bin linear-d2 histogram ---
            for (int g = tid; g < ctot; g += 256) {
                float d2 = __uint_as_float((unsigned)(cand[g] >> 11));
                atomicAdd(&hist[min((int)(d2 * BINSCALE), 255)], 1);
            }
            __syncthreads();

            // --- Block inclusive scan over bins, find crossing bin ---
            int v = hist[tid];
            int incl = v;
            #pragma unroll
            for (int o = 1; o < 32; o <<= 1) {
                int t = __shfl_up_sync(0xffffffffu, incl, o);
                if (lane >= o) incl += t;
            }
            if (lane == 31) wtot[w] = incl;
            __syncthreads();
            if (tid == 0) {
                int r = 0;
                #pragma unroll
                for (int q = 0; q < 8; q++) { int t = wtot[q]; wtot[q] = r; r += t; }
            }
            __syncthreads();
            incl += wtot[w];
            int excl = incl - v;
            if (excl < KSEL && KSEL <= incl) { s_B = tid; s_targ = KSEL - excl; }
            __syncthreads();
            const int B = s_B;

            // --- Gather bucket + fused below-bucket energy ---
            for (int g = tid; g < ctot; g += 256) {
                unsigned long long key = cand[g];
                float d2 = __uint_as_float((unsigned)(key >> 11));
                int bin = min((int)(d2 * BINSCALE), 255);
                if (bin < B) {
                    local += pair_energy(d2, (int)(key & 2047ull), seqb, aa_base);
                } else if (bin == B) {
                    int pos = atomicAdd(&s_bcnt, 1);
                    if (pos < BCAP) buf[pos] = key;
                }
            }
            __syncthreads();
            const int bc = s_bcnt;

            if (bc <= BCAP) {
                // --- Exact threshold by warp-0 rank count (unique keys) ---
                if (tid < 32) {
                    const int tg = s_targ;
                    for (int c = lane; c < bc; c += 32) {
                        unsigned long long key = buf[c];
                        int rank = 0;
                        for (int t = 0; t < bc; t++) rank += (buf[t] < key);
                        if (rank == tg - 1) s_T = key;
                    }
                }
                __syncthreads();
                const unsigned long long T = s_T;
                for (int g = tid; g < bc; g += 256) {
                    unsigned long long key = buf[g];
                    if (key <= T) {
                        float d2 = __uint_as_float((unsigned)(key >> 11));
                        local += pair_energy(d2, (int)(key & 2047ull), seqb, aa_base);
                    }
                }
            } else {
                // --- Bucket overflow (never expected): exact flat radix ---
                local = 0.f;
                if (tid == 0) { s_pref = 0ull; s_targ = KSEL; }
                __syncthreads();
                for (int pass = 0; pass < 6; pass++) {
                    const int shift = 40 - 8 * pass;
                    hist[tid] = 0;
                    __syncthreads();
                    const unsigned long long hp = s_pref >> (shift + 8);
                    for (int g = tid; g < ctot; g += 256) {
                        unsigned long long key = cand[g];
                        if ((key >> (shift + 8)) == hp)
                            atomicAdd(&hist[(int)((key >> shift) & 255)], 1);
                    }
                    __syncthreads();
                    if (tid < 32) {
                        const int base = tid * 8;
                        int c8[8]; int ssum = 0;
                        #pragma unroll
                        for (int t = 0; t < 8; t++) { c8[t] = hist[base + t]; ssum += c8[t]; }
                        int incl2 = ssum;
                        #pragma unroll
                        for (int o = 1; o < 32; o <<= 1) {
                            int t = __shfl_up_sync(0xffffffffu, incl2, o);
                            if (tid >= o) incl2 += t;
                        }
                        int excl2 = incl2 - ssum;
                        const int tgt = s_targ;
                        const unsigned long long pref = s_pref;
                        __syncwarp();
                        int run = excl2;
                        #pragma unroll
                        for (int t = 0; t < 8; t++) {
                            if (run < tgt && tgt <= run + c8[t]) {
                                s_pref = pref | ((unsigned long long)(base + t) << shift);
                                s_targ = tgt - run;
                            }
                            run += c8[t];
                        }
                    }
                    __syncthreads();
                }
                const unsigned long long T = s_pref;
                for (int g = tid; g < ctot; g += 256) {
                    unsigned long long key = cand[g];
                    if (key <= T) {
                        float d2 = __uint_as_float((unsigned)(key >> 11));
                        local += pair_energy(d2, (int)(key & 2047ull), seqb, aa_base);
                    }
                }
            }
        } else {
            // ctot <= KSEL: every candidate contributes
            for (int g = tid; g < ctot; g += 256) {
                unsigned long long key = cand[g];
                float d2 = __uint_as_float((unsigned)(key >> 11));
                local += pair_energy(d2, (int)(key & 2047ull), seqb, aa_base);
            }
        }
    } else {
        // ===== SLOW PATH (ctot > CANDN, never expected): segment-major =====
        hist[tid] = 0;
        __syncthreads();
        #pragma unroll 1
        for (int s = 0; s < 8; s++) {
            const int cs = s_cnt[s];
            for (int c = tid; c < cs; c += 256) {
                float d2 = __uint_as_float((unsigned)(seg[(s << 8) + c] >> 11));
                atomicAdd(&hist[min((int)(d2 * BINSCALE), 255)], 1);
            }
        }
        __syncthreads();

        int v = hist[tid];
        int incl = v;
        #pragma unroll
        for (int o = 1; o < 32; o <<= 1) {
            int t = __shfl_up_sync(0xffffffffu, incl, o);
            if (lane >= o) incl += t;
        }
        if (lane == 31) wtot[w] = incl;
        __syncthreads();
        if (tid == 0) {
            int r = 0;
            #pragma unroll
            for (int q = 0; q < 8; q++) { int t = wtot[q]; wtot[q] = r; r += t; }
        }
        __syncthreads();
        incl += wtot[w];
        int excl = incl - v;
        if (excl < KSEL && KSEL <= incl) { s_B = tid; s_targ = KSEL - excl; }
        __syncthreads();
        const int B = s_B;

        #pragma unroll 1
        for (int s = 0; s < 8; s++) {
            const int cs = s_cnt[s];
            for (int c = tid; c < cs; c += 256) {
                unsigned long long key = seg[(s << 8) + c];
                float d2 = __uint_as_float((unsigned)(key >> 11));
                int bin = min((int)(d2 * BINSCALE), 255);
                if (bin == B) {
                    int pos = atomicAdd(&s_bcnt, 1);
                    if (pos < BCAP) buf[pos] = key;
                }
            }
        }
        __syncthreads();
        const int bc = s_bcnt;

        if (bc <= BCAP) {
            if (tid < 32) {
                const int tg = s_targ;
                for (int c = lane; c < bc; c += 32) {
                    unsigned long long key = buf[c];
                    int rank = 0;
                    for (int t = 0; t < bc; t++) rank += (buf[t] < key);
                    if (rank == tg - 1) s_T = key;
                }
            }
            __syncthreads();
        } else {
            if (tid == 0) { s_pref = 0ull; s_targ = KSEL; }
            __syncthreads();
            for (int pass = 0; pass < 6; pass++) {
                const int shift = 40 - 8 * pass;
                hist[tid] = 0;
                __syncthreads();
                const unsigned long long hp = s_pref >> (shift + 8);
                for (int s = 0; s < 8; s++) {
                    const int cs = s_cnt[s];
                    for (int c = tid; c < cs; c += 256) {
                        unsigned long long key = seg[(s << 8) + c];
                        if ((key >> (shift + 8)) == hp)
                            atomicAdd(&hist[(int)((key >> shift) & 255)], 1);
                    }
                }
                __syncthreads();
                if (tid < 32) {
                    const int base = tid * 8;
                    int c8[8]; int ssum = 0;
                    #pragma unroll
                    for (int t = 0; t < 8; t++) { c8[t] = hist[base + t]; ssum += c8[t]; }
                    int incl2 = ssum;
                    #pragma unroll
                    for (int o = 1; o < 32; o <<= 1) {
                        int t = __shfl_up_sync(0xffffffffu, incl2, o);
                        if (tid >= o) incl2 += t;
                    }
                    int excl2 = incl2 - ssum;
                    const int tgt = s_targ;
                    const unsigned long long pref = s_pref;
                    __syncwarp();
                    int run = excl2;
                    #pragma unroll
                    for (int t = 0; t < 8; t++) {
                        if (run < tgt && tgt <= run + c8[t]) {
                            s_pref = pref | ((unsigned long long)(base + t) << shift);
                            s_targ = tgt - run;
                        }
                        run += c8[t];
                    }
                }
                __syncthreads();
            }
            if (tid == 0) s_T = s_pref;
            __syncthreads();
        }

        const unsigned long long T = s_T;
        #pragma unroll 1
        for (int s = 0; s < 8; s++) {
            const int cs = s_cnt[s];
            for (int c = tid; c < cs; c += 256) {
                unsigned long long key = seg[(s << 8) + c];
                if (key <= T) {
                    float d2 = __uint_as_float((unsigned)(key >> 11));
                    local += pair_energy(d2, (int)(key & 2047ull), seqb, aa_base);
                }
            }
        }
    }

    // --- Deterministic block reduction ---
    #pragma unroll
    for (int o = 16; o > 0; o >>= 1)
        local += __shfl_down_sync(0xffffffffu, local, o);
    if (lane == 0) wsum[w] = local;
    __syncthreads();
    if (tid == 0) {
        float s = 0.f;
        #pragma unroll
        for (int q = 0; q < 8; q++) s += wsum[q];
        g_rowsum[row] = s;
    }
}

// ---------------------------------------------------------------------------
// Kernel 2: deterministic per-batch reduction
// ---------------------------------------------------------------------------
__global__ void __launch_bounds__(256) reduce_kernel(float* __restrict__ out)
{
    __shared__ float s[256];
    const int b = blockIdx.x;
    const int tid = threadIdx.x;
    float v = 0.f;
    for (int i = tid; i < Ln; i += 256) v += g_rowsum[b * Ln + i];
    s[tid] = v;
    __syncthreads();
    for (int o = 128; o > 0; o >>= 1) {
        if (tid < o) s[tid] += s[tid + o];
        __syncthreads();
    }
    if (tid == 0) out[b] = s[0];
}

// ---------------------------------------------------------------------------
extern "C" void kernel_launch(void* const* d_in, const int* in_sizes, int n_in,
                              void* d_out, int out_size)
{
    const float* R       = (const float*)d_in[0];
    const int*   seq     = (const int*)  d_in[1];
    const float* emb     = (const float*)d_in[2];
    const float* W1      = (const float*)d_in[3];
    const float* b1      = (const float*)d_in[4];
    const float* W2      = (const float*)d_in[5];
    const float* b2      = (const float*)d_in[6];
    const float* W3      = (const float*)d_in[7];
    const float* b3      = (const float*)d_in[8];
    float* out = (float*)d_out;

    pad_kernel<<<(Bn * Ln) / 256, 256>>>(R);
    table_kernel<<<NAA * NAA / 2, 512>>>(emb, W1, b1, W2, b2, W3, b3);
    topk_energy_kernel<<<Bn * Ln, 256>>>(seq);
    reduce_kernel<<<Bn, 256>>>(out);
}

// round 16
// speedup vs baseline: 1.1219x; 1.1195x over previous
#include <cuda_runtime.h>
#include <cuda_bf16.h>
#include <math.h>

#define Bn    8
#define Ln    2048
#define KSEL  64
#define EXCL  3
#define NAA   20
#define EMB   16
#define MD    7
#define D2CUT 144.0f      // r >= 12 -> smoothstep == 0 -> zero energy
#define BCAP  256         // bucket capacity before radix fallback
#define CANDN 1024        // flat candidate buffer per row
#define SEGC  128         // per-warp-window per-row segment capacity
#define BINSCALE (256.0f / 144.0f)

// Scratch (device globals: no allocation allowed)
__device__ float g_tab[NAA * NAA * MD];       // softplus(MLP(aa_i,aa_j))

// ---------------------------------------------------------------------------
// Kernel 0: exact fp32 MLP over 400 AA pairs -> 400x7 table. Also zeroes out.
// 2 pairs/block (ILP-2), 512 threads, 4-way K-split (short serial chains).
// ---------------------------------------------------------------------------
__global__ void __launch_bounds__(512) table_kernel(
    const float* __restrict__ emb,
    const float* __restrict__ W1, const float* __restrict__ b1,
    const float* __restrict__ W2, const float* __restrict__ b2,
    const float* __restrict__ W3, const float* __restrict__ b3,
    float* __restrict__ out)
{
    __shared__ float x[2][48];
    __shared__ float h1[2][128];
    __shared__ float h2[2][128];
    __shared__ float part[2][4][128];

    const int p0 = blockIdx.x * 2;
    const int tid = threadIdx.x;
    const int n = tid & 127;
    const int q4 = tid >> 7;            // 0..3

    if (blockIdx.x == 0 && tid < Bn) out[tid] = 0.f;   // stream-ordered zero

    if (tid < 2 * EMB) {
        int pr = tid >> 4, c = tid & 15;
        int p = p0 + pr;
        float ei = emb[(p / NAA) * EMB + c];
        float ej = emb[(p % NAA) * EMB + c];
        x[pr][c] = ei; x[pr][EMB + c] = ej; x[pr][2 * EMB + c] = ei * ej;
    }
    __syncthreads();

    {   // Layer 1: K=48, 4 x 12
        float a0 = 0.f, a1 = 0.f;
        const int k0 = q4 * 12;
        #pragma unroll
        for (int k = 0; k < 12; k++) {
            float w = W1[(k0 + k) * 128 + n];
            a0 = fmaf(x[0][k0 + k], w, a0);
            a1 = fmaf(x[1][k0 + k], w, a1);
        }
        part[0][q4][n] = a0; part[1][q4][n] = a1;
    }
    __syncthreads();
    if (q4 < 2)
        h1[q4][n] = fmaxf(b1[n] + part[q4][0][n] + part[q4][1][n]
                                + part[q4][2][n] + part[q4][3][n], 0.f);
    __syncthreads();

    {   // Layer 2: K=128, 4 x 32
        float a0 = 0.f, a1 = 0.f;
        const int k0 = q4 * 32;
        #pragma unroll
        for (int k = 0; k < 32; k++) {
            float w = W2[(k0 + k) * 128 + n];
            a0 = fmaf(h1[0][k0 + k], w, a0);
            a1 = fmaf(h1[1][k0 + k], w, a1);
        }
        part[0][q4][n] = a0; part[1][q4][n] = a1;
    }
    __syncthreads();
    if (q4 < 2)
        h2[q4][n] = fmaxf(b2[n] + part[q4][0][n] + part[q4][1][n]
                                + part[q4][2][n] + part[q4][3][n], 0.f);
    __syncthreads();

    if (tid < 2 * MD * 4) {   // Layer 3: K=128, 4 x 32, 7 outs x 2 pairs
        int pr = tid / 28, rem = tid % 28;
        int m = rem % MD, qq = rem / MD;
        float a = 0.f;
        const int k0 = qq * 32;
        #pragma unroll
        for (int k = 0; k < 32; k++)
            a = fmaf(h2[pr][k0 + k], W3[(k0 + k) * MD + m], a);
        part[pr][qq][m] = a;
    }
    __syncthreads();
    if (tid < 2 * MD) {
        int pr = tid / MD, m = tid % MD;
        float a = b3[m] + part[pr][0][m] + part[pr][1][m]
                        + part[pr][2][m] + part[pr][3][m];
        float sp = fmaxf(a, 0.f) + log1pf(expf(-fabsf(a)));  // jax softplus
        g_tab[(p0 + pr) * MD + m] = sp;
    }
}

// ---------------------------------------------------------------------------
// Per-pair energy: table lookup + anchored RBF product chain + smoothstep.
// ---------------------------------------------------------------------------
__device__ __forceinline__ float pair_energy(float d2, int jj,
                                             const int* __restrict__ seqb,
                                             int aa_base)
{
    float r = sqrtf(d2);
    int aj = __ldg(seqb + jj);
    const float* tp = g_tab + (aa_base + aj) * MD;
    const float C2  = 0.13533528323661270f;      // e^-2
    const float C6  = 2.4787521766663585e-3f;    // e^-6
    const float C10 = 4.5399929762484854e-5f;    // e^-10
    float t  = r - 8.f;
    float p3 = __expf(-2.f * t * t);
    float G  = __expf( 4.f * t);
    float Gi = __expf(-4.f * t);
    float p4 = p3 * G  * C2;
    float p5 = p4 * G  * C6;
    float p6 = p5 * G  * C10;
    float p2 = p3 * Gi * C2;
    float p1 = p2 * Gi * C6;
    float p0 = p1 * Gi * C10;
    float att = tp[0] * p0 + tp[1] * p1 + tp[2] * p2 + tp[3] * p3
              + tp[4] * p4 + tp[5] * p5 + tp[6] * p6;
    float tt = fminf(fmaxf((r - 10.f) * 0.5f, 0.f), 1.f);
    float sw = 1.f - tt * tt * (3.f - 2.f * tt);
    return -att * sw;
}

// ---------------------------------------------------------------------------
// Warp-0 radix digit resolution over a 256-bin histogram (8 bins/lane).
// ---------------------------------------------------------------------------
__device__ __forceinline__ void resolve8(const int* __restrict__ hist,
                                         unsigned long long* s_pref,
                                         int* s_targ, int shift, int tid)
{
    if (tid < 32) {
        const int base = tid * 8;
        int c8[8]; int ssum = 0;
        #pragma unroll
        for (int t = 0; t < 8; t++) { c8[t] = hist[base + t]; ssum += c8[t]; }
        int incl = ssum;
        #pragma unroll
        for (int o = 1; o < 32; o <<= 1) {
            int t = __shfl_up_sync(0xffffffffu, incl, o);
            if (tid >= o) incl += t;
        }
        int excl = incl - ssum;
        const int tgt = *s_targ;
        const unsigned long long pref = *s_pref;
        __syncwarp();
        int run = excl;
        #pragma unroll
        for (int t = 0; t < 8; t++) {
            if (run < tgt && tgt <= run + c8[t]) {
                *s_pref = pref | ((unsigned long long)(base + t) << shift);
                *s_targ = tgt - run;
            }
            run += c8[t];
        }
    }
}

// ---------------------------------------------------------------------------
// Kernel 1: TWO rows per CTA sharing the scan loads. R13 flat select per row.
// __launch_bounds__(256, 8) pins 8 CTAs/SM. key = (bits(d2) << 11) | j.
// Per-window cap 128 with a storage-free exact radix fallback (never taken).
// Final: one atomicAdd per CTA into out[b].
// ---------------------------------------------------------------------------
__global__ void __launch_bounds__(256, 8) topk_energy_kernel(
    const float* __restrict__ R, const int* __restrict__ seq,
    float* __restrict__ out)
{
    __shared__ unsigned long long seg[2 * 8 * SEGC];   // 16 KB (2 rows)
    __shared__ unsigned long long cand[CANDN];         // 8 KB
    __shared__ unsigned long long buf[BCAP];           // 2 KB
    __shared__ int hist[256];
    __shared__ int s_cnt[16];                          // [row*8 + warp]
    __shared__ int wtot[8];
    __shared__ float wsum[8];
    __shared__ int s_B, s_targ, s_bcnt;
    __shared__ unsigned long long s_T;
    __shared__ unsigned long long s_pref;

    const int tid = threadIdx.x;
    const int w = tid >> 5, lane = tid & 31;
    const unsigned lanelt = (1u << lane) - 1u;
    const int b = blockIdx.x >> 10;
    const int ipair = (blockIdx.x & 1023) << 1;        // rows ipair, ipair+1
    const float* __restrict__ Rb = R + (size_t)b * Ln * 3;
    const int* __restrict__ seqb = seq + b * Ln;

    const float x0 = Rb[3 * ipair],     y0 = Rb[3 * ipair + 1], z0 = Rb[3 * ipair + 2];
    const float x1 = Rb[3 * ipair + 3], y1 = Rb[3 * ipair + 4], z1 = Rb[3 * ipair + 5];

    // --- Scan: warp w owns j in [256w, 256w+256); both rows share loads ---
    int cnt0 = 0, cnt1 = 0;
    #pragma unroll
    for (int it = 0; it < 8; it++) {
        const int j = (w << 8) + (it << 5) + lane;
        const float xj = Rb[3 * j], yj = Rb[3 * j + 1], zj = Rb[3 * j + 2];

        float dx = x0 - xj, dy = y0 - yj, dz = z0 - zj;
        float d20 = fmaf(dx, dx, fmaf(dy, dy, fmaf(dz, dz, 1e-12f)));
        dx = x1 - xj; dy = y1 - yj; dz = z1 - zj;
        float d21 = fmaf(dx, dx, fmaf(dy, dy, fmaf(dz, dz, 1e-12f)));

        bool p0 = (d20 < D2CUT) && ((unsigned)(j - ipair + EXCL) > 2u * EXCL);
        unsigned m0 = __ballot_sync(0xffffffffu, p0);
        if (p0) {
            int pos = cnt0 + __popc(m0 & lanelt);
            if (pos < SEGC)
                seg[(w << 7) + pos] =
                    (((unsigned long long)__float_as_uint(d20)) << 11) | (unsigned)j;
        }
        cnt0 += __popc(m0);

        bool p1 = (d21 < D2CUT) && ((unsigned)(j - ipair - 1 + EXCL) > 2u * EXCL);
        unsigned m1 = __ballot_sync(0xffffffffu, p1);
        if (p1) {
            int pos = cnt1 + __popc(m1 & lanelt);
            if (pos < SEGC)
                seg[8 * SEGC + (w << 7) + pos] =
                    (((unsigned long long)__float_as_uint(d21)) << 11) | (unsigned)j;
        }
        cnt1 += __popc(m1);
    }
    if (lane == 0) { s_cnt[w] = cnt0; s_cnt[8 + w] = cnt1; }
    __syncthreads();

    float local = 0.f;

    #pragma unroll 1
    for (int r = 0; r < 2; r++) {
        const int i = ipair + r;
        const int aa_base = __ldg(seqb + i) * NAA;
        float rloc = 0.f;

        int ctot = 0; int ovf = 0;
        #pragma unroll
        for (int s = 0; s < 8; s++) {
            int c = s_cnt[r * 8 + s];
            ctot += c;
            ovf |= (c > SEGC);
        }

        if (!ovf && ctot <= CANDN) {
            // ===================== FLAT FAST PATH =====================
            {
                int off = 0;
                #pragma unroll
                for (int s = 0; s < 8; s++) {
                    int cs = s_cnt[r * 8 + s];
                    if (tid < cs) cand[off + tid] = seg[r * 8 * SEGC + (s << 7) + tid];
                    off += cs;
                }
            }
            if (tid == 0) { s_bcnt = 0; s_T = ~0ull; }
            hist[tid] = 0;
            __syncthreads();

            if (ctot > KSEL) {
                // --- 1-round 256-bin linear-d2 histogram ---
                for (int g = tid; g < ctot; g += 256) {
                    float d2 = __uint_as_float((unsigned)(cand[g] >> 11));
                    atomicAdd(&hist[min((int)(d2 * BINSCALE), 255)], 1);
                }
                __syncthreads();

                // --- Block inclusive scan over bins, find crossing bin ---
                int v = hist[tid];
                int incl = v;
                #pragma unroll
                for (int o = 1; o < 32; o <<= 1) {
                    int t = __shfl_up_sync(0xffffffffu, incl, o);
                    if (lane >= o) incl += t;
                }
                if (lane == 31) wtot[w] = incl;
                __syncthreads();
                if (tid == 0) {
                    int rr = 0;
                    #pragma unroll
                    for (int q = 0; q < 8; q++) { int t = wtot[q]; wtot[q] = rr; rr += t; }
                }
                __syncthreads();
                incl += wtot[w];
                int excl = incl - v;
                if (excl < KSEL && KSEL <= incl) { s_B = tid; s_targ = KSEL - excl; }
                __syncthreads();
                const int B = s_B;

                // --- Gather bucket + fused below-bucket energy ---
                for (int g = tid; g < ctot; g += 256) {
                    unsigned long long key = cand[g];
                    float d2 = __uint_as_float((unsigned)(key >> 11));
                    int bin = min((int)(d2 * BINSCALE), 255);
                    if (bin < B) {
                        rloc += pair_energy(d2, (int)(key & 2047ull), seqb, aa_base);
                    } else if (bin == B) {
                        int pos = atomicAdd(&s_bcnt, 1);
                        if (pos < BCAP) buf[pos] = key;
                    }
                }
                __syncthreads();
                const int bc = s_bcnt;

                if (bc <= BCAP) {
                    // --- Exact threshold by warp-0 rank count (unique keys) ---
                    if (tid < 32) {
                        const int tg = s_targ;
                        for (int c = lane; c < bc; c += 32) {
                            unsigned long long key = buf[c];
                            int rank = 0;
                            for (int t = 0; t < bc; t++) rank += (buf[t] < key);
                            if (rank == tg - 1) s_T = key;
                        }
                    }
                    __syncthreads();
                    const unsigned long long T = s_T;
                    for (int g = tid; g < bc; g += 256) {
                        unsigned long long key = buf[g];
                        if (key <= T) {
                            float d2 = __uint_as_float((unsigned)(key >> 11));
                            rloc += pair_energy(d2, (int)(key & 2047ull), seqb, aa_base);
                        }
                    }
                } else {
                    // --- Bucket overflow (never expected): exact flat radix ---
                    rloc = 0.f;
                    if (tid == 0) { s_pref = 0ull; s_targ = KSEL; }
                    __syncthreads();
                    for (int pass = 0; pass < 6; pass++) {
                        const int shift = 40 - 8 * pass;
                        hist[tid] = 0;
                        __syncthreads();
                        const unsigned long long hp = s_pref >> (shift + 8);
                        for (int g = tid; g < ctot; g += 256) {
                            unsigned long long key = cand[g];
                            if ((key >> (shift + 8)) == hp)
                                atomicAdd(&hist[(int)((key >> shift) & 255)], 1);
                        }
                        __syncthreads();
                        resolve8(hist, &s_pref, &s_targ, shift, tid);
                        __syncthreads();
                    }
                    const unsigned long long T = s_pref;
                    for (int g = tid; g < ctot; g += 256) {
                        unsigned long long key = cand[g];
                        if (key <= T) {
                            float d2 = __uint_as_float((unsigned)(key >> 11));
                            rloc += pair_energy(d2, (int)(key & 2047ull), seqb, aa_base);
                        }
                    }
                }
            } else {
                // ctot <= KSEL: every candidate contributes
                for (int g = tid; g < ctot; g += 256) {
                    unsigned long long key = cand[g];
                    float d2 = __uint_as_float((unsigned)(key >> 11));
                    rloc += pair_energy(d2, (int)(key & 2047ull), seqb, aa_base);
                }
            }
        } else {
            // ===== STORAGE-FREE EXACT FALLBACK (never expected) =====
            const float xi = Rb[3 * i], yi = Rb[3 * i + 1], zi = Rb[3 * i + 2];
            unsigned long long T = ~0ull;
            if (ctot > KSEL) {
                if (tid == 0) { s_pref = 0ull; s_targ = KSEL; }
                __syncthreads();
                for (int pass = 0; pass < 6; pass++) {
                    const int shift = 40 - 8 * pass;
                    hist[tid] = 0;
                    __syncthreads();
                    const unsigned long long hp = s_pref >> (shift + 8);
                    for (int j = tid; j < Ln; j += 256) {
                        float dx = xi - Rb[3 * j];
                        float dy = yi - Rb[3 * j + 1];
                        float dz = zi - Rb[3 * j + 2];
                        float d2 = fmaf(dx, dx, fmaf(dy, dy, fmaf(dz, dz, 1e-12f)));
                        if (d2 < D2CUT && (unsigned)(j - i + EXCL) > 2u * EXCL) {
                            unsigned long long key =
                                (((unsigned long long)__float_as_uint(d2)) << 11)
                                | (unsigned)j;
                            if ((key >> (shift + 8)) == hp)
                                atomicAdd(&hist[(int)((key >> shift) & 255)], 1);
                        }
                    }
                    __syncthreads();
                    resolve8(hist, &s_pref, &s_targ, shift, tid);
                    __syncthreads();
                }
                T = s_pref;
            }
            for (int j = tid; j < Ln; j += 256) {
                float dx = xi - Rb[3 * j];
                float dy = yi - Rb[3 * j + 1];
                float dz = zi - Rb[3 * j + 2];
                float d2 = fmaf(dx, dx, fmaf(dy, dy, fmaf(dz, dz, 1e-12f)));
                if (d2 < D2CUT && (unsigned)(j - i + EXCL) > 2u * EXCL) {
                    unsigned long long key =
                        (((unsigned long long)__float_as_uint(d2)) << 11)
                        | (unsigned)j;
                    if (key <= T)
                        rloc += pair_energy(d2, j, seqb, aa_base);
                }
            }
        }

        local += rloc;
        __syncthreads();     // protect cand/buf/hist reuse across rows
    }

    // --- Deterministic block reduction, then one atomic per CTA ---
    #pragma unroll
    for (int o = 16; o > 0; o >>= 1)
        local += __shfl_down_sync(0xffffffffu, local, o);
    if (lane == 0) wsum[w] = local;
    __syncthreads();
    if (tid == 0) {
        float s = 0.f;
        #pragma unroll
        for (int q = 0; q < 8; q++) s += wsum[q];
        atomicAdd(out + b, s);
    }
}

// ---------------------------------------------------------------------------
extern "C" void kernel_launch(void* const* d_in, const int* in_sizes, int n_in,
                              void* d_out, int out_size)
{
    const float* R       = (const float*)d_in[0];
    const int*   seq     = (const int*)  d_in[1];
    const float* emb     = (const float*)d_in[2];
    const float* W1      = (const float*)d_in[3];
    const float* b1      = (const float*)d_in[4];
    const float* W2      = (const float*)d_in[5];
    const float* b2      = (const float*)d_in[6];
    const float* W3      = (const float*)d_in[7];
    const float* b3      = (const float*)d_in[8];
    float* out = (float*)d_out;

    table_kernel<<<NAA * NAA / 2, 512>>>(emb, W1, b1, W2, b2, W3, b3, out);
    topk_energy_kernel<<<Bn * Ln / 2, 256>>>(R, seq, out);
}